// round 1
// baseline (speedup 1.0000x reference)
#include <cuda_runtime.h>
#include <cuda_bf16.h>
#include <math.h>

// Problem constants
#define D 64
#define KPROTO 128
#define TM 64          // rows per CTA
#define TK 64          // prototypes per CTA (K split in 2)

// Scratch for projected prototypes (no cudaMalloc allowed)
__device__ float g_p[KPROTO * D];     // projected prototypes, row-major [k][d]
__device__ float g_p2[KPROTO];        // squared norms of projected prototypes

// ---------------------------------------------------------------------------
// Kernel 0: project prototypes onto the Poincare ball, precompute p^2.
// maxnorm = (1 - BALL_EPS)/sqrt(c) = 0.999 (c = 1)
// ---------------------------------------------------------------------------
__global__ void proj_kernel(const float* __restrict__ proto) {
    int k = threadIdx.x;   // 128 threads, one per prototype
    float v[D];
    float s = 0.0f;
#pragma unroll
    for (int d = 0; d < D; ++d) {
        v[d] = proto[k * D + d];
        s += v[d] * v[d];
    }
    float n = fmaxf(sqrtf(s), 1e-15f);
    float scale = fminf(1.0f, 0.999f / n);
#pragma unroll
    for (int d = 0; d < D; ++d) {
        g_p[k * D + d] = v[d] * scale;
    }
    g_p2[k] = s * scale * scale;
}

// ---------------------------------------------------------------------------
// Main kernel: per (n, k):
//   xy = <x_n, p_k>,  x2 = |x_n|^2,  p2 = |p_k|^2
//   A = 1 - 2 xy + p2 ; B = 1 - x2
//   |num|^2 = A^2 x2 - 2AB xy + B^2 p2
//   den = max(1 - 2 xy + x2 p2, 1e-15)
//   z = min(|num|/den, 1 - 1e-5)
//   out = -(2 atanh z)^2 = -(ln((1+z)/(1-z)))^2
// ---------------------------------------------------------------------------
__global__ void __launch_bounds__(256, 4)
geo_kernel(const float* __restrict__ x, float* __restrict__ out) {
    __shared__ float x_s[D * TM];    // [d][r], stride TM
    __shared__ float p_s[D * TK];    // [d][k], stride TK
    __shared__ float x2_s[TM];
    __shared__ float p2_s[TK];

    const int tid = threadIdx.x;
    const int n0  = blockIdx.x * TM;
    const int k0  = blockIdx.y * TK;

    // Load x tile and p tile transposed into smem.
    // Contiguous smem index per lane -> conflict-free STS; global reads are
    // strided but both tensors are small / L2-resident.
#pragma unroll
    for (int it = 0; it < (D * TM) / 256; ++it) {
        int s = it * 256 + tid;
        int d = s >> 6;        // s / 64
        int r = s & 63;        // s % 64
        x_s[s] = x[(n0 + r) * D + d];
        p_s[s] = g_p[(k0 + r) * D + d];
    }
    if (tid < TK) p2_s[tid] = g_p2[k0 + tid];
    __syncthreads();

    // Per-row |x|^2 (threads 0..63, strided over d -> distinct banks per lane)
    if (tid < TM) {
        float s = 0.0f;
#pragma unroll
        for (int d = 0; d < D; ++d) {
            float v = x_s[d * TM + tid];
            s += v * v;
        }
        x2_s[tid] = s;
    }
    __syncthreads();

    // 4x4 register tile per thread
    const int tx = tid & 15;   // k group: k = tx*4 .. tx*4+3
    const int ty = tid >> 4;   // row group: r = ty*4 .. ty*4+3

    const float4* xs4 = reinterpret_cast<const float4*>(x_s);
    const float4* ps4 = reinterpret_cast<const float4*>(p_s);

    float acc[4][4] = {};
#pragma unroll
    for (int d = 0; d < D; ++d) {
        float4 a = xs4[d * (TM / 4) + ty];   // x rows ty*4..+3 at this d
        float4 b = ps4[d * (TK / 4) + tx];   // p cols tx*4..+3 at this d
        acc[0][0] += a.x * b.x; acc[0][1] += a.x * b.y; acc[0][2] += a.x * b.z; acc[0][3] += a.x * b.w;
        acc[1][0] += a.y * b.x; acc[1][1] += a.y * b.y; acc[1][2] += a.y * b.z; acc[1][3] += a.y * b.w;
        acc[2][0] += a.z * b.x; acc[2][1] += a.z * b.y; acc[2][2] += a.z * b.z; acc[2][3] += a.z * b.w;
        acc[3][0] += a.w * b.x; acc[3][1] += a.w * b.y; acc[3][2] += a.w * b.z; acc[3][3] += a.w * b.w;
    }

    // Epilogue + coalesced float4 stores
    float p2v[4];
#pragma unroll
    for (int j = 0; j < 4; ++j) p2v[j] = p2_s[tx * 4 + j];

#pragma unroll
    for (int i = 0; i < 4; ++i) {
        const int n = n0 + ty * 4 + i;
        const float x2v = x2_s[ty * 4 + i];
        const float B = 1.0f - x2v;
        float4 res;
        float* resp = reinterpret_cast<float*>(&res);
#pragma unroll
        for (int j = 0; j < 4; ++j) {
            float xy = acc[i][j];
            float A = 1.0f - 2.0f * xy + p2v[j];
            float num2 = A * A * x2v - 2.0f * A * B * xy + B * B * p2v[j];
            num2 = fmaxf(num2, 0.0f);
            float den = fmaxf(1.0f - 2.0f * xy + x2v * p2v[j], 1e-15f);
            float z = fminf(__fdividef(sqrtf(num2), den), 1.0f - 1e-5f);
            float dist = __logf(__fdividef(1.0f + z, 1.0f - z));  // 2*atanh(z)
            resp[j] = -dist * dist;
        }
        *reinterpret_cast<float4*>(&out[(size_t)n * KPROTO + k0 + tx * 4]) = res;
    }
}

// ---------------------------------------------------------------------------
extern "C" void kernel_launch(void* const* d_in, const int* in_sizes, int n_in,
                              void* d_out, int out_size) {
    // Identify inputs by element count (x: 16384*64, prototypes: 128*64)
    const float* x;
    const float* proto;
    int xs;
    if (in_sizes[0] == KPROTO * D) {
        proto = (const float*)d_in[0];
        x     = (const float*)d_in[1];
        xs    = in_sizes[1];
    } else {
        x     = (const float*)d_in[0];
        proto = (const float*)d_in[1];
        xs    = in_sizes[0];
    }
    const int N = xs / D;   // 16384
    float* out = (float*)d_out;

    proj_kernel<<<1, KPROTO>>>(proto);
    dim3 grid(N / TM, KPROTO / TK);
    geo_kernel<<<grid, 256>>>(x, out);
}

// round 2
// speedup vs baseline: 2.4725x; 2.4725x over previous
#include <cuda_runtime.h>
#include <cuda_bf16.h>
#include <math.h>

#define D      64
#define TM     128
#define KPROTO 128
#define NTH    256

// ---------------------------------------------------------------------------
// Fused kernel: per CTA of 128 x-rows vs all 128 prototypes.
//  - projects prototypes (redundantly per CTA, trivially cheap, L2-hot)
//  - smem GEMM with 8x8 register tiles (64 FFMA : 4 LDS.128 per d)
//  - algebraic epilogue: |num|^2 = A^2 x2 - 2AB xy + B^2 p2,
//    dist = ln((den+s)/(den-s)), out = -dist^2
// ---------------------------------------------------------------------------
__global__ void __launch_bounds__(NTH)
geo_kernel(const float* __restrict__ x, const float* __restrict__ proto,
           float* __restrict__ out) {
    extern __shared__ float smem[];
    float* x_s  = smem;               // [d][r]  64 x 128
    float* p_s  = smem + D * TM;      // [d][k]  64 x 128
    float* x2_s = smem + 2 * D * TM;  // 128
    float* p2_s = x2_s + TM;          // 128

    const int tid = threadIdx.x;
    const int n0  = blockIdx.x * TM;

    // ---- x tile fill: LDG.128 + in-register 4x4 transpose + STS.128 ----
    {
        const float4* x4  = reinterpret_cast<const float4*>(x);
        float4*       xs4 = reinterpret_cast<float4*>(x_s);
        const int R  = tid & 31;   // granule row: covers rows 4R..4R+3
        const int cc = tid >> 5;   // d-chunk group 0..7
        #pragma unroll
        for (int h = 0; h < 2; ++h) {
            const int c = cc + 8 * h;  // d-chunk: d = 4c..4c+3
            float4 m0 = x4[(size_t)(n0 + 4 * R + 0) * 16 + c];
            float4 m1 = x4[(size_t)(n0 + 4 * R + 1) * 16 + c];
            float4 m2 = x4[(size_t)(n0 + 4 * R + 2) * 16 + c];
            float4 m3 = x4[(size_t)(n0 + 4 * R + 3) * 16 + c];
            xs4[(4 * c + 0) * 32 + R] = make_float4(m0.x, m1.x, m2.x, m3.x);
            xs4[(4 * c + 1) * 32 + R] = make_float4(m0.y, m1.y, m2.y, m3.y);
            xs4[(4 * c + 2) * 32 + R] = make_float4(m0.z, m1.z, m2.z, m3.z);
            xs4[(4 * c + 3) * 32 + R] = make_float4(m0.w, m1.w, m2.w, m3.w);
        }
    }

    // ---- prototype projection onto ball (threads 0..127, one per proto) ----
    if (tid < KPROTO) {
        const float4* p4 = reinterpret_cast<const float4*>(proto) + (size_t)tid * 16;
        float s = 0.f;
        #pragma unroll
        for (int i = 0; i < 16; ++i) {
            float4 v = p4[i];
            s += v.x * v.x + v.y * v.y + v.z * v.z + v.w * v.w;
        }
        const float n     = fmaxf(sqrtf(s), 1e-15f);
        const float scale = fminf(1.0f, 0.999f / n);  // (1-BALL_EPS)/sqrt(c)
        #pragma unroll
        for (int i = 0; i < 16; ++i) {
            float4 v = p4[i];
            p_s[(4 * i + 0) * KPROTO + tid] = v.x * scale;
            p_s[(4 * i + 1) * KPROTO + tid] = v.y * scale;
            p_s[(4 * i + 2) * KPROTO + tid] = v.z * scale;
            p_s[(4 * i + 3) * KPROTO + tid] = v.w * scale;
        }
        p2_s[tid] = s * scale * scale;
    }
    __syncthreads();

    // ---- per-row |x|^2 (threads 0..127, conflict-free column reads) ----
    if (tid < TM) {
        float s = 0.f;
        #pragma unroll
        for (int d = 0; d < D; ++d) {
            float v = x_s[d * TM + tid];
            s = fmaf(v, v, s);
        }
        x2_s[tid] = s;
    }
    __syncthreads();

    // ---- main GEMM: 8x8 per thread ----
    const int ty = tid >> 4;  // rows 8*ty .. 8*ty+7   (a-granules 2ty, 2ty+1)
    const int tx = tid & 15;  // cols {4tx..4tx+3} and {64+4tx..64+4tx+3}
    const float4* xs4 = reinterpret_cast<const float4*>(x_s);
    const float4* ps4 = reinterpret_cast<const float4*>(p_s);

    float acc[8][8];
    #pragma unroll
    for (int i = 0; i < 8; ++i)
        #pragma unroll
        for (int j = 0; j < 8; ++j) acc[i][j] = 0.f;

    #pragma unroll 8
    for (int d = 0; d < D; ++d) {
        float4 a0 = xs4[d * 32 + 2 * ty];
        float4 a1 = xs4[d * 32 + 2 * ty + 1];
        float4 b0 = ps4[d * 32 + tx];       // conflict-free: 16 consecutive granules
        float4 b1 = ps4[d * 32 + tx + 16];
        float av[8] = {a0.x, a0.y, a0.z, a0.w, a1.x, a1.y, a1.z, a1.w};
        float bv[8] = {b0.x, b0.y, b0.z, b0.w, b1.x, b1.y, b1.z, b1.w};
        #pragma unroll
        for (int i = 0; i < 8; ++i)
            #pragma unroll
            for (int j = 0; j < 8; ++j)
                acc[i][j] = fmaf(av[i], bv[j], acc[i][j]);
    }

    // ---- epilogue ----
    float p2v[8];
    #pragma unroll
    for (int j = 0; j < 4; ++j) {
        p2v[j]     = p2_s[4 * tx + j];
        p2v[j + 4] = p2_s[64 + 4 * tx + j];
    }

    #pragma unroll
    for (int i = 0; i < 8; ++i) {
        const int   n   = n0 + 8 * ty + i;
        const float x2v = x2_s[8 * ty + i];
        const float B   = 1.0f - x2v;
        float r0[4], r1[4];
        #pragma unroll
        for (int j = 0; j < 8; ++j) {
            const float xy = acc[i][j];
            const float p2 = p2v[j];
            const float A  = 1.0f + p2 - 2.0f * xy;
            float num2 = A * A * x2v - 2.0f * A * B * xy + B * B * p2;
            num2 = fmaxf(num2, 1e-30f);
            const float den = fmaxf(1.0f - 2.0f * xy + x2v * p2, 1e-15f);
            float sN = num2 * rsqrtf(num2);          // sqrt(num2), 1 MUFU
            sN = fminf(sN, 0.99999f * den);          // z <= 1 - 1e-5
            const float dist = __logf(__fdividef(den + sN, den - sN)); // 2*atanh(z)
            const float r = -dist * dist;
            if (j < 4) r0[j] = r; else r1[j - 4] = r;
        }
        *reinterpret_cast<float4*>(&out[(size_t)n * KPROTO + 4 * tx]) =
            make_float4(r0[0], r0[1], r0[2], r0[3]);
        *reinterpret_cast<float4*>(&out[(size_t)n * KPROTO + 64 + 4 * tx]) =
            make_float4(r1[0], r1[1], r1[2], r1[3]);
    }
}

// ---------------------------------------------------------------------------
extern "C" void kernel_launch(void* const* d_in, const int* in_sizes, int n_in,
                              void* d_out, int out_size) {
    const float* x;
    const float* proto;
    int xs;
    if (in_sizes[0] == KPROTO * D) {
        proto = (const float*)d_in[0];
        x     = (const float*)d_in[1];
        xs    = in_sizes[1];
    } else {
        x     = (const float*)d_in[0];
        proto = (const float*)d_in[1];
        xs    = in_sizes[0];
    }
    const int N = xs / D;  // 16384
    float* out = (float*)d_out;

    const size_t smem_bytes = (2 * D * TM + 2 * TM) * sizeof(float);  // 66560 B
    cudaFuncSetAttribute(geo_kernel, cudaFuncAttributeMaxDynamicSharedMemorySize,
                         (int)smem_bytes);
    geo_kernel<<<N / TM, NTH, smem_bytes>>>(x, proto, out);
}